// round 15
// baseline (speedup 1.0000x reference)
#include <cuda_runtime.h>
#include <cuda_bf16.h>
#include <cuda_fp16.h>
#include <cstdint>

#define C_DIM 128
#define G_DIM 8
#define KNN   16
#define EPS_BN 1e-5f
#define N_CTX_MAX 131072
#define M_Q_MAX   16384

// ---------------- scratch (static device memory; no runtime allocation) -----
__device__ float   g_kw  [(size_t)N_CTX_MAX * G_DIM];
__device__ float   g_qw  [(size_t)M_Q_MAX   * G_DIM];
__device__ float   g_WpwT[G_DIM * C_DIM];
__device__ float   g_pwb [G_DIM];
__device__ __align__(16) __half2 g_Hs2h[(size_t)M_Q_MAX * G_DIM * 128];  // (U,H), 64 MB
__device__ float   g_sums[(size_t)M_Q_MAX * G_DIM];
__device__ float   g_wsr [(size_t)M_Q_MAX * G_DIM];
__device__ __align__(16) uint4 g_Wsplit[2][2][2176];

typedef unsigned long long ull;

__device__ __forceinline__ void ffma2(ull& d, ull a, ull b) {
    asm("fma.rn.f32x2 %0, %1, %2, %3;" : "=l"(d) : "l"(a), "l"(b), "l"(d));
}
__device__ __forceinline__ ull pack2(float x) {
    ull r; unsigned u = __float_as_uint(x);
    asm("mov.b64 %0, {%1, %1};" : "=l"(r) : "r"(u));
    return r;
}
__device__ __forceinline__ void unpack2(ull v, float& lo, float& hi) {
    lo = __uint_as_float((unsigned)v);
    hi = __uint_as_float((unsigned)(v >> 32));
}

// bf16 HMMA m16n8k16
__device__ __forceinline__ void mma_bf16(float* d, uint32_t a0, uint32_t a1,
                                         uint32_t a2, uint32_t a3,
                                         uint32_t b0, uint32_t b1) {
    asm volatile(
        "mma.sync.aligned.m16n8k16.row.col.f32.bf16.bf16.f32 "
        "{%0,%1,%2,%3}, {%4,%5,%6,%7}, {%8,%9}, {%0,%1,%2,%3};"
        : "+f"(d[0]), "+f"(d[1]), "+f"(d[2]), "+f"(d[3])
        : "r"(a0), "r"(a1), "r"(a2), "r"(a3), "r"(b0), "r"(b1));
}
// fp16 HMMA m16n8k16, fp32 accum
__device__ __forceinline__ void mma_f16(float* d, uint32_t a0, uint32_t a1,
                                        uint32_t a2, uint32_t a3,
                                        uint32_t b0, uint32_t b1) {
    asm volatile(
        "mma.sync.aligned.m16n8k16.row.col.f32.f16.f16.f32 "
        "{%0,%1,%2,%3}, {%4,%5,%6,%7}, {%8,%9}, {%0,%1,%2,%3};"
        : "+f"(d[0]), "+f"(d[1]), "+f"(d[2]), "+f"(d[3])
        : "r"(a0), "r"(a1), "r"(a2), "r"(a3), "r"(b0), "r"(b1));
}

__device__ __forceinline__ uint32_t bf2_u32(__nv_bfloat162 h) {
    uint32_t u; __builtin_memcpy(&u, &h, 4); return u;
}
__device__ __forceinline__ void split16(const float* v, uint4* outH, uint4* outL) {
    uint32_t hp[8], lp[8];
#pragma unroll
    for (int p = 0; p < 8; p++) {
        float a0 = v[2 * p], a1 = v[2 * p + 1];
        __nv_bfloat162 h = __floats2bfloat162_rn(a0, a1);
        float r0 = a0 - __bfloat162float(h.x);
        float r1 = a1 - __bfloat162float(h.y);
        __nv_bfloat162 l = __floats2bfloat162_rn(r0, r1);
        hp[p] = bf2_u32(h); lp[p] = bf2_u32(l);
    }
    outH[0] = make_uint4(hp[0], hp[4], hp[1], hp[5]);
    outH[1] = make_uint4(hp[2], hp[6], hp[3], hp[7]);
    outL[0] = make_uint4(lp[0], lp[4], lp[1], lp[5]);
    outL[1] = make_uint4(lp[2], lp[6], lp[3], lp[7]);
}

// ---------------- K0w: precompute bf16-split packed W tiles ------------------
__global__ void k0w_prep(const float* __restrict__ Wk, const float* __restrict__ Wq) {
    const int task = blockIdx.x * 256 + threadIdx.x;
    const int mat = task >> 10, rem = task & 1023;
    const int n = rem >> 3, kg = rem & 7;
    const float* W = mat ? Wq : Wk;
    float v[16];
#pragma unroll
    for (int j = 0; j < 16; j++) v[j] = W[(size_t)(kg * 16 + j) * C_DIM + n];
    uint4 oh[2], ol[2];
    split16(v, oh, ol);
    const int base = n * 17 + kg * 2;
    g_Wsplit[mat][0][base]     = oh[0];
    g_Wsplit[mat][0][base + 1] = oh[1];
    g_Wsplit[mat][1][base]     = ol[0];
    g_Wsplit[mat][1][base + 1] = ol[1];
}

// ---------------- K0: tiny prep ----------------------------------------------
#define SMEM_K0_TOTAL ((128 * 132 + 1024) * 4)
__global__ void k0_prep(const float* __restrict__ Wp2,
                        const float* __restrict__ Ww1,
                        const float* __restrict__ bp2) {
    extern __shared__ float sp[];
    float* WpS = sp;
    float* W1s = sp + 128 * 132;
    const int tid = threadIdx.x;
    for (int i = tid; i < 4096; i += 256) {
        int r = i >> 5, q = i & 31;
        *(float4*)&WpS[r * 132 + q * 4] = *(const float4*)&Wp2[r * C_DIM + q * 4];
    }
    if (tid < 256) *(float4*)&W1s[tid * 4] = *(const float4*)&Ww1[tid * 4];
    __syncthreads();

    if (tid < 128) {
        const int c = tid;
        float acc[G_DIM];
#pragma unroll
        for (int g = 0; g < G_DIM; g++) acc[g] = 0.f;
        const float* wr = &WpS[c * 132];
#pragma unroll 8
        for (int c2 = 0; c2 < C_DIM; c2++) {
            float a = wr[c2];
#pragma unroll
            for (int g = 0; g < G_DIM; g++) acc[g] = fmaf(a, W1s[c2 * G_DIM + g], acc[g]);
        }
#pragma unroll
        for (int g = 0; g < G_DIM; g++) g_WpwT[g * C_DIM + c] = acc[g];
    } else if (tid < 128 + G_DIM) {
        const int g = tid - 128;
        float s = 0.f;
        for (int c2 = 0; c2 < C_DIM; c2++) s = fmaf(bp2[c2], W1s[c2 * G_DIM + g], s);
        g_pwb[g] = s;
    }
}

// ---------------- K12: fused context+query pass (B from global, occ 3) -------
#define K1_ROWB 272
__device__ __forceinline__ uint32_t k1_off(int row, int k) {
    int p = k >> 1;
    return (uint32_t)row * K1_ROWB + (uint32_t)(k >> 4) * 32
         + (uint32_t)(p & 3) * 8 + (uint32_t)((p >> 2) & 1) * 4;
}

#define SM_AH   0          // 17408
#define SM_AL   17408      // 17408
#define SM_PAR  34816      // 2048
#define SM_W1T  36864      // 4224
#define SM_KS   0          // float[64][132] reuses A region (33792 <= 34816)
#define SMEM_K12_TOTAL 41216

__launch_bounds__(256, 3)
__global__ void k12_proj(const float* __restrict__ cf, const float* __restrict__ qf,
                         const float* __restrict__ bk,
                         const float* __restrict__ gk, const float* __restrict__ betak,
                         const float* __restrict__ bq,
                         const float* __restrict__ gq, const float* __restrict__ betaq,
                         const float* __restrict__ Ww1, int NB) {
    extern __shared__ char smem[];
    const int tid = threadIdx.x;
    const int wid = tid >> 5;
    const int lane = tid & 31;
    const int grp = lane >> 2, tig = lane & 3;

    const bool ctx = (int)blockIdx.x < NB;
    const int bm0 = (ctx ? (int)blockIdx.x : (int)blockIdx.x - NB) * 64;
    const float* feat = ctx ? cf : qf;
    const float* bb   = ctx ? bk : bq;
    const float* gg   = ctx ? gk : gq;
    const float* be   = ctx ? betak : betaq;
    float* dst        = ctx ? g_kw : g_qw;
    const int mat     = ctx ? 0 : 1;

    // ---- A tile fill (hi/lo bf16 split, fragment-packed) ----
#pragma unroll
    for (int s2 = 0; s2 < 2; s2++) {
        int task = tid + s2 * 256;
        int row = task >> 3, kg = task & 7;
        const float4* src = (const float4*)&feat[(size_t)(bm0 + row) * C_DIM + kg * 16];
        float v[16];
        float4 x0 = src[0], x1 = src[1], x2 = src[2], x3 = src[3];
        v[0]=x0.x; v[1]=x0.y; v[2]=x0.z; v[3]=x0.w;
        v[4]=x1.x; v[5]=x1.y; v[6]=x1.z; v[7]=x1.w;
        v[8]=x2.x; v[9]=x2.y; v[10]=x2.z; v[11]=x2.w;
        v[12]=x3.x; v[13]=x3.y; v[14]=x3.z; v[15]=x3.w;
        uint4 oh[2], ol[2];
        split16(v, oh, ol);
        uint4* dH = (uint4*)(smem + SM_AH + row * K1_ROWB + kg * 32);
        uint4* dL = (uint4*)(smem + SM_AL + row * K1_ROWB + kg * 32);
        dH[0] = oh[0]; dH[1] = oh[1];
        dL[0] = ol[0]; dL[1] = ol[1];
    }
    const float rs = rsqrtf(1.f + EPS_BN);
    if (tid < C_DIM) {
        float4 pp; pp.x = bb[tid]; pp.y = gg[tid] * rs; pp.z = be[tid]; pp.w = 0.f;
        *(float4*)(smem + SM_PAR + tid * 16) = pp;
    }
    {
        float* W1T = (float*)(smem + SM_W1T);
        for (int i = tid; i < 1024; i += 256) {
            int c = i >> 3, g = i & 7;
            W1T[g * 132 + c] = Ww1[i];
        }
    }
    __syncthreads();

    // ---- MMA: A from smem, B fragments straight from global (L1-resident) ----
    const int rbase = (wid & 3) * 16;
    const int cbase = (wid >> 2) * 64;
    float acc[8][4];
#pragma unroll
    for (int nt = 0; nt < 8; nt++)
#pragma unroll
        for (int q = 0; q < 4; q++) acc[nt][q] = 0.f;

    const uint32_t aoff_lo = k1_off(rbase + grp, 0) + tig * 8;
    const uint32_t aoff_hi = k1_off(rbase + grp + 8, 0) + tig * 8;
    const char* WBH = (const char*)g_Wsplit[mat][0];
    const char* WBL = (const char*)g_Wsplit[mat][1];

#pragma unroll
    for (int ks = 0; ks < 8; ks++) {
        const uint32_t kb = ks * 32;
        ull alo_h = *(const ull*)(smem + SM_AH + aoff_lo + kb);
        ull ahi_h = *(const ull*)(smem + SM_AH + aoff_hi + kb);
        ull alo_l = *(const ull*)(smem + SM_AL + aoff_lo + kb);
        ull ahi_l = *(const ull*)(smem + SM_AL + aoff_hi + kb);
        uint32_t a0h = (uint32_t)alo_h, a2h = (uint32_t)(alo_h >> 32);
        uint32_t a1h = (uint32_t)ahi_h, a3h = (uint32_t)(ahi_h >> 32);
        uint32_t a0l = (uint32_t)alo_l, a2l = (uint32_t)(alo_l >> 32);
        uint32_t a1l = (uint32_t)ahi_l, a3l = (uint32_t)(ahi_l >> 32);
#pragma unroll
        for (int nt = 0; nt < 8; nt++) {
            uint32_t boff = (uint32_t)(cbase + nt * 8 + grp) * K1_ROWB + kb + tig * 8;
            ull bh = __ldg((const ull*)(WBH + boff));
            ull bl = __ldg((const ull*)(WBL + boff));
            uint32_t b0h = (uint32_t)bh, b1h = (uint32_t)(bh >> 32);
            uint32_t b0l = (uint32_t)bl, b1l = (uint32_t)(bl >> 32);
            mma_bf16(acc[nt], a0h, a1h, a2h, a3h, b0h, b1h);
            mma_bf16(acc[nt], a0h, a1h, a2h, a3h, b0l, b1l);
            mma_bf16(acc[nt], a0l, a1l, a2l, a3l, b0h, b1h);
        }
    }
    __syncthreads();

    {
        float* ks_s = (float*)(smem + SM_KS);
        const float4* par = (const float4*)(smem + SM_PAR);
        const int r0 = rbase + grp, r1 = r0 + 8;
#pragma unroll
        for (int nt = 0; nt < 8; nt++) {
            int col = cbase + nt * 8 + tig * 2;
            float4 p0 = par[col], p1 = par[col + 1];
            float2 lo, hi;
            lo.x = fmaxf(fmaf(acc[nt][0] + p0.x, p0.y, p0.z), 0.f);
            lo.y = fmaxf(fmaf(acc[nt][1] + p1.x, p1.y, p1.z), 0.f);
            hi.x = fmaxf(fmaf(acc[nt][2] + p0.x, p0.y, p0.z), 0.f);
            hi.y = fmaxf(fmaf(acc[nt][3] + p1.x, p1.y, p1.z), 0.f);
            *(float2*)&ks_s[r0 * 132 + col] = lo;
            *(float2*)&ks_s[r1 * 132 + col] = hi;
        }
    }
    __syncthreads();

    {
        const float* ks_s = (const float*)(smem + SM_KS);
        const float* W1T  = (const float*)(smem + SM_W1T);
#pragma unroll
        for (int s2 = 0; s2 < 2; s2++) {
            int task = tid + s2 * 256;
            int row = task >> 3, g = task & 7;
            const float4* kr = (const float4*)&ks_s[row * 132];
            const float4* wr = (const float4*)&W1T[g * 132];
            ull A = 0, B = 0, C = 0, D = 0;
#pragma unroll
            for (int j = 0; j < 32; j += 2) {
                float4 k0 = kr[j],     w0 = wr[j];
                float4 k1 = kr[j + 1], w1 = wr[j + 1];
                ffma2(A, ((const ull*)&k0)[0], ((const ull*)&w0)[0]);
                ffma2(B, ((const ull*)&k0)[1], ((const ull*)&w0)[1]);
                ffma2(C, ((const ull*)&k1)[0], ((const ull*)&w1)[0]);
                ffma2(D, ((const ull*)&k1)[1], ((const ull*)&w1)[1]);
            }
            float a0, a1, b0, b1, c0, c1, d0, d1;
            unpack2(A, a0, a1); unpack2(B, b0, b1);
            unpack2(C, c0, c1); unpack2(D, d0, d1);
            dst[(size_t)(bm0 + row) * G_DIM + g] =
                ((a0 + a1) + (b0 + b1)) + ((c0 + c1) + (d0 + d1));
        }
    }
}

// ---------------- K3: attention weights + U/H accumulation (FFMA2, occ6) -----
struct S3 {
    float WpwT[G_DIM * 132];
    float ww2s[G_DIM * G_DIM];
    float hs[2][KNN * 132];
    float e_s[KNN * G_DIM];
    float psum[4 * G_DIM];
    float wpsum[4 * G_DIM];
    float pos[2][KNN * 4];
    float kwg[2][KNN * G_DIM];
    float qw[2][G_DIM];
    float msk[2][KNN];
    int   idx[2][KNN];
};

__device__ __forceinline__ void gatherK(S3* s, const int* __restrict__ knn,
                                        const float* __restrict__ qcoord,
                                        const float* __restrict__ ccoord,
                                        int m, int p, int k) {
    int id = knn[(size_t)m * KNN + k];
    float mk = id >= 0 ? 1.f : 0.f;
    int id0 = id >= 0 ? id : 0;
    s->idx[p][k] = id0;
    s->msk[p][k] = mk;
    float qx = qcoord[m * 3 + 0], qy = qcoord[m * 3 + 1], qz = qcoord[m * 3 + 2];
    s->pos[p][k * 4 + 0] = (ccoord[(size_t)id0 * 3 + 0] - qx) * mk;
    s->pos[p][k * 4 + 1] = (ccoord[(size_t)id0 * 3 + 1] - qy) * mk;
    s->pos[p][k * 4 + 2] = (ccoord[(size_t)id0 * 3 + 2] - qz) * mk;
    const float4* kwp = (const float4*)&g_kw[(size_t)id0 * G_DIM];
    float4 a = kwp[0], b = kwp[1];
    float* kd = &s->kwg[p][k * 8];
    kd[0] = a.x * mk; kd[1] = a.y * mk; kd[2] = a.z * mk; kd[3] = a.w * mk;
    kd[4] = b.x * mk; kd[5] = b.y * mk; kd[6] = b.z * mk; kd[7] = b.w * mk;
}

__device__ __forceinline__ void p4_packed(S3& s, int bp, int mp, int c, int t,
                                          const float* cfpre) {
    ull uu01 = 0, uu23 = 0, uu45 = 0, uu67 = 0;
    ull hh01 = 0, hh23 = 0, hh45 = 0, hh67 = 0;
#pragma unroll
    for (int k = 0; k < KNN; k++) {
        float hk = s.hs[bp][k * 132 + c];
        ull hkp = pack2(hk);
        ull cvp = pack2(cfpre[k]);
        float4 ea = *(const float4*)&s.e_s[k * 8];
        float4 eb = *(const float4*)&s.e_s[k * 8 + 4];
        ull e01 = ((const ull*)&ea)[0], e23 = ((const ull*)&ea)[1];
        ull e45 = ((const ull*)&eb)[0], e67 = ((const ull*)&eb)[1];
        ffma2(uu01, cvp, e01); ffma2(uu23, cvp, e23);
        ffma2(uu45, cvp, e45); ffma2(uu67, cvp, e67);
        ffma2(hh01, hkp, e01); ffma2(hh23, hkp, e23);
        ffma2(hh45, hkp, e45); ffma2(hh67, hkp, e67);
    }
    float uu[G_DIM], hh[G_DIM];
    unpack2(uu01, uu[0], uu[1]); unpack2(uu23, uu[2], uu[3]);
    unpack2(uu45, uu[4], uu[5]); unpack2(uu67, uu[6], uu[7]);
    unpack2(hh01, hh[0], hh[1]); unpack2(hh23, hh[2], hh[3]);
    unpack2(hh45, hh[4], hh[5]); unpack2(hh67, hh[6], hh[7]);
    __half2* baseh = &g_Hs2h[(size_t)mp * (G_DIM * 128)];
#pragma unroll
    for (int g2 = 0; g2 < G_DIM; g2++)
        baseh[g2 * 128 + c] = __floats2half2_rn(uu[g2], hh[g2]);
    if (t < G_DIM) {
        g_sums[(size_t)mp * G_DIM + t] =
            s.psum[t] + s.psum[8 + t] + s.psum[16 + t] + s.psum[24 + t];
        g_wsr[(size_t)mp * G_DIM + t] =
            s.wpsum[t] + s.wpsum[8 + t] + s.wpsum[16 + t] + s.wpsum[24 + t];
    }
}

__launch_bounds__(128, 6)
__global__ void k3_attn(const float* __restrict__ qcoord, const float* __restrict__ ccoord,
                        const int*   __restrict__ knn, const float* __restrict__ cf,
                        const float* __restrict__ Wp1, const float* __restrict__ bp1,
                        const float* __restrict__ gp1, const float* __restrict__ betap1,
                        const float* __restrict__ bw1, const float* __restrict__ gw1,
                        const float* __restrict__ betaw1,
                        const float* __restrict__ Ww2, const float* __restrict__ bw2) {
    __shared__ S3 s;
    const int t = threadIdx.x;
    const int c = t;
    const int kB = t >> 3, gB = t & 7;
    const int w4 = t >> 5;
    const int lane = t & 31;
    const int lbase = lane & ~7;

    for (int i = t; i < G_DIM * C_DIM; i += 128) {
        int r = i >> 7, cc2 = i & 127;
        s.WpwT[r * 132 + cc2] = g_WpwT[i];
    }
    if (t < G_DIM * G_DIM) s.ww2s[t] = Ww2[t];

    const float rs  = rsqrtf(1.f + EPS_BN);
    const float sp1 = gp1[c] * rs;
    const float wf0 = Wp1[c] * sp1, wf1 = Wp1[C_DIM + c] * sp1, wf2 = Wp1[2 * C_DIM + c] * sp1;
    const float hb  = fmaf(bp1[c], sp1, betap1[c]);
    const float sw1  = gw1[gB] * rs;
    const float wb1f = fmaf(bw1[gB], sw1, betaw1[gB]);
    const float pwbB = g_pwb[gB];
    const float bw2B = bw2[gB];

    const int mb = blockIdx.x * 8;
    float cfpre[KNN];

    if (t < KNN)   gatherK(&s, knn, qcoord, ccoord, mb, 0, t);
    if (t < G_DIM) s.qw[0][t] = g_qw[(size_t)mb * G_DIM + t];
    __syncthreads();

    for (int qi = 0; qi < 8; qi++) {
        const int b = qi & 1;
        const int m = mb + qi;

        {
#pragma unroll
            for (int k = 0; k < KNN; k++) {
                const float* pp = &s.pos[b][k * 4];
                s.hs[b][k * 132 + c] =
                    fmaxf(fmaf(wf0, pp[0], fmaf(wf1, pp[1], fmaf(wf2, pp[2], hb))), 0.f);
            }
            if (qi < 7) {
                if (t < KNN)   gatherK(&s, knn, qcoord, ccoord, m + 1, b ^ 1, t);
                if (t < G_DIM) s.qw[b ^ 1][t] = g_qw[(size_t)(m + 1) * G_DIM + t];
            }
            if (qi > 0) p4_packed(s, b ^ 1, m - 1, c, t, cfpre);
        }
        __syncthreads();

        {
            float init = s.kwg[b][t] - s.qw[b][gB] + pwbB;
            ull A = (ull)__float_as_uint(init);
            ull B = 0, C = 0, D = 0;
            const float4* hr = (const float4*)&s.hs[b][kB * 132];
            const float4* wr = (const float4*)&s.WpwT[gB * 132];
#pragma unroll
            for (int j = 0; j < 32; j += 2) {
                float4 h0 = hr[j],     w0 = wr[j];
                float4 h1 = hr[j + 1], w1 = wr[j + 1];
                ffma2(A, ((const ull*)&h0)[0], ((const ull*)&w0)[0]);
                ffma2(B, ((const ull*)&h0)[1], ((const ull*)&w0)[1]);
                ffma2(C, ((const ull*)&h1)[0], ((const ull*)&w1)[0]);
                ffma2(D, ((const ull*)&h1)[1], ((const ull*)&w1)[1]);
            }
            float a0, a1, b0, b1, c0, c1, d0, d1;
            unpack2(A, a0, a1); unpack2(B, b0, b1);
            unpack2(C, c0, c1); unpack2(D, d0, d1);
            float part = ((a0 + a1) + (b0 + b1)) + ((c0 + c1) + (d0 + d1));
            float ts = fmaxf(fmaf(part, sw1, wb1f), 0.f);

            float lg = bw2B;
#pragma unroll
            for (int g2 = 0; g2 < G_DIM; g2++)
                lg = fmaf(__shfl_sync(0xffffffffu, ts, lbase + g2), s.ww2s[g2 * G_DIM + gB], lg);

            float e  = __expf(lg);
            float mk = s.msk[b][kB];
            float em = e * mk;
            s.e_s[t] = em;
            float es = e;
            es += __shfl_xor_sync(0xffffffffu, es, 8);
            es += __shfl_xor_sync(0xffffffffu, es, 16);
            float esm = em;
            esm += __shfl_xor_sync(0xffffffffu, esm, 8);
            esm += __shfl_xor_sync(0xffffffffu, esm, 16);
            if (lane < 8) { s.psum[w4 * 8 + gB] = es; s.wpsum[w4 * 8 + gB] = esm; }

            const int* ix = s.idx[b];
#pragma unroll
            for (int k = 0; k < KNN; k++) cfpre[k] = cf[(size_t)ix[k] * C_DIM + c];
        }
        __syncthreads();
    }

    p4_packed(s, 1, mb + 7, c, t, cfpre);
}

// ---------------- K4: epilogue via fp16 HMMA ---------------------------------
#define K4_AS_OFF 0
#define K4_BS_OFF (64 * 132 * 4)
#define SMEM_K4_TOTAL (64 * 132 * 4 + 16 * 132 * 4)   // 42240 B
__launch_bounds__(256, 4)
__global__ void k4_out(const float* __restrict__ Wv, const float* __restrict__ Wp2,
                       const float* __restrict__ bv, const float* __restrict__ bp2,
                       float* __restrict__ out) {
    extern __shared__ char s4raw[];
    __half2* As = (__half2*)(s4raw + K4_AS_OFF);   // [64][132]
    __half2* Bs = (__half2*)(s4raw + K4_BS_OFF);   // [16][132]
    const int m0 = blockIdx.x * 64;
    const int g  = blockIdx.y;
    const int tid = threadIdx.x;

    for (int i = tid; i < 2048; i += 256) {
        int r = i >> 5, q = i & 31;
        *(uint4*)&As[r * 132 + q * 4] =
            *(const uint4*)&g_Hs2h[((size_t)(m0 + r) * G_DIM + g) * 128 + q * 4];
    }
    for (int i = tid; i < 2048; i += 256) {
        int c2 = i >> 4, cc = i & 15;
        float wv = Wv[(size_t)c2 * C_DIM + g * 16 + cc];
        float wp = Wp2[(size_t)c2 * C_DIM + g * 16 + cc];
        Bs[cc * 132 + c2] = __floats2half2_rn(wv, wp);
    }
    __syncthreads();

    const int wid = tid >> 5, lane = tid & 31;
    const int grp = lane >> 2, tig = lane & 3;
    const int mt = wid & 3, nt = wid >> 2;
    const __half2* Ar0 = &As[(mt * 16 + grp) * 132];
    const __half2* Ar1 = &As[(mt * 16 + grp + 8) * 132];
    const __half2* Bc  = &Bs[(nt * 8 + grp) * 132];

    float acc[4] = {0.f, 0.f, 0.f, 0.f};
#pragma unroll
    for (int ks = 0; ks < 16; ks++) {
        const int cb = ks * 8;
        uint32_t a0 = *(const uint32_t*)&Ar0[cb + tig];
        uint32_t a1 = *(const uint32_t*)&Ar1[cb + tig];
        uint32_t a2 = *(const uint32_t*)&Ar0[cb + tig + 4];
        uint32_t a3 = *(const uint32_t*)&Ar1[cb + tig + 4];
        uint32_t b0 = *(const uint32_t*)&Bc[cb + tig];
        uint32_t b1 = *(const uint32_t*)&Bc[cb + tig + 4];
        mma_f16(acc, a0, a1, a2, a3, b0, b1);
    }

    const int mA = m0 + mt * 16 + grp;
    const int mB = mA + 8;
    const float invA = 1.f / g_sums[(size_t)mA * G_DIM + g];
    const float wsA  = g_wsr[(size_t)mA * G_DIM + g];
    const float invB = 1.f / g_sums[(size_t)mB * G_DIM + g];
    const float wsB  = g_wsr[(size_t)mB * G_DIM + g];
    const int c0 = g * 16 + nt * 8 + 2 * tig;
    const float bb0 = bv[c0] + bp2[c0];
    const float bb1 = bv[c0 + 1] + bp2[c0 + 1];
    float2 oA, oB;
    oA.x = (acc[0] + bb0 * wsA) * invA;
    oA.y = (acc[1] + bb1 * wsA) * invA;
    oB.x = (acc[2] + bb0 * wsB) * invB;
    oB.y = (acc[3] + bb1 * wsB) * invB;
    *(float2*)&out[(size_t)mA * C_DIM + c0] = oA;
    *(float2*)&out[(size_t)mB * C_DIM + c0] = oB;
}

// ---------------- launch -----------------------------------------------------
extern "C" void kernel_launch(void* const* d_in, const int* in_sizes, int n_in,
                              void* d_out, int out_size) {
    const float* qf     = (const float*)d_in[0];
    const float* cf     = (const float*)d_in[1];
    const float* qc     = (const float*)d_in[2];
    const float* cc     = (const float*)d_in[3];
    const float* Wq     = (const float*)d_in[4];
    const float* bq     = (const float*)d_in[5];
    const float* gq     = (const float*)d_in[6];
    const float* betaq  = (const float*)d_in[7];
    const float* Wk     = (const float*)d_in[8];
    const float* bk     = (const float*)d_in[9];
    const float* gk     = (const float*)d_in[10];
    const float* betak  = (const float*)d_in[11];
    const float* Wv     = (const float*)d_in[12];
    const float* bv     = (const float*)d_in[13];
    const float* Wp1    = (const float*)d_in[14];
    const float* bp1    = (const float*)d_in[15];
    const float* gp1    = (const float*)d_in[16];
    const float* betap1 = (const float*)d_in[17];
    const float* Wp2    = (const float*)d_in[18];
    const float* bp2    = (const float*)d_in[19];
    const float* Ww1    = (const float*)d_in[20];
    const float* bw1    = (const float*)d_in[21];
    const float* gw1    = (const float*)d_in[22];
    const float* betaw1 = (const float*)d_in[23];
    const float* Ww2    = (const float*)d_in[24];
    const float* bw2    = (const float*)d_in[25];
    const int*   knn    = (const int*)d_in[26];
    float* out = (float*)d_out;

    const int M = in_sizes[0] / C_DIM;
    const int N = in_sizes[1] / C_DIM;
    const int NB = N / 64, MB = M / 64;

    k0w_prep<<<8, 256>>>(Wk, Wq);

    cudaFuncSetAttribute(k0_prep, cudaFuncAttributeMaxDynamicSharedMemorySize,
                         SMEM_K0_TOTAL);
    k0_prep<<<1, 256, SMEM_K0_TOTAL>>>(Wp2, Ww1, bp2);

    cudaFuncSetAttribute(k12_proj, cudaFuncAttributeMaxDynamicSharedMemorySize,
                         SMEM_K12_TOTAL);
    k12_proj<<<NB + MB, 256, SMEM_K12_TOTAL>>>(cf, qf, bk, gk, betak,
                                               bq, gq, betaq, Ww1, NB);

    k3_attn<<<M / 8, 128>>>(qc, cc, knn, cf, Wp1, bp1, gp1, betap1,
                            bw1, gw1, betaw1, Ww2, bw2);

    cudaFuncSetAttribute(k4_out, cudaFuncAttributeMaxDynamicSharedMemorySize,
                         SMEM_K4_TOTAL);
    dim3 g4(M / 64, G_DIM);
    k4_out<<<g4, 256, SMEM_K4_TOTAL>>>(Wv, Wp2, bv, bp2, out);
}

// round 16
// speedup vs baseline: 1.1678x; 1.1678x over previous
#include <cuda_runtime.h>
#include <cuda_bf16.h>
#include <cuda_fp16.h>
#include <cstdint>

#define C_DIM 128
#define G_DIM 8
#define KNN   16
#define EPS_BN 1e-5f
#define N_CTX_MAX 131072
#define M_Q_MAX   16384

// ---------------- scratch (static device memory; no runtime allocation) -----
__device__ float   g_kw  [(size_t)N_CTX_MAX * G_DIM];
__device__ float   g_qw  [(size_t)M_Q_MAX   * G_DIM];
__device__ float   g_WpwT[G_DIM * C_DIM];
__device__ float   g_pwb [G_DIM];
__device__ __align__(16) __half2 g_Hs2h[(size_t)M_Q_MAX * G_DIM * 128];  // (U,H), 64 MB
__device__ float   g_sums[(size_t)M_Q_MAX * G_DIM];
__device__ float   g_wsr [(size_t)M_Q_MAX * G_DIM];
__device__ __align__(16) uint4 g_Wsplit[2][2][2176];

typedef unsigned long long ull;

__device__ __forceinline__ void ffma2(ull& d, ull a, ull b) {
    asm("fma.rn.f32x2 %0, %1, %2, %3;" : "=l"(d) : "l"(a), "l"(b), "l"(d));
}
__device__ __forceinline__ ull pack2(float x) {
    ull r; unsigned u = __float_as_uint(x);
    asm("mov.b64 %0, {%1, %1};" : "=l"(r) : "r"(u));
    return r;
}
__device__ __forceinline__ void unpack2(ull v, float& lo, float& hi) {
    lo = __uint_as_float((unsigned)v);
    hi = __uint_as_float((unsigned)(v >> 32));
}

// bf16 HMMA m16n8k16
__device__ __forceinline__ void mma_bf16(float* d, uint32_t a0, uint32_t a1,
                                         uint32_t a2, uint32_t a3,
                                         uint32_t b0, uint32_t b1) {
    asm volatile(
        "mma.sync.aligned.m16n8k16.row.col.f32.bf16.bf16.f32 "
        "{%0,%1,%2,%3}, {%4,%5,%6,%7}, {%8,%9}, {%0,%1,%2,%3};"
        : "+f"(d[0]), "+f"(d[1]), "+f"(d[2]), "+f"(d[3])
        : "r"(a0), "r"(a1), "r"(a2), "r"(a3), "r"(b0), "r"(b1));
}
// fp16 HMMA m16n8k16, fp32 accum
__device__ __forceinline__ void mma_f16(float* d, uint32_t a0, uint32_t a1,
                                        uint32_t a2, uint32_t a3,
                                        uint32_t b0, uint32_t b1) {
    asm volatile(
        "mma.sync.aligned.m16n8k16.row.col.f32.f16.f16.f32 "
        "{%0,%1,%2,%3}, {%4,%5,%6,%7}, {%8,%9}, {%0,%1,%2,%3};"
        : "+f"(d[0]), "+f"(d[1]), "+f"(d[2]), "+f"(d[3])
        : "r"(a0), "r"(a1), "r"(a2), "r"(a3), "r"(b0), "r"(b1));
}

__device__ __forceinline__ uint32_t bf2_u32(__nv_bfloat162 h) {
    uint32_t u; __builtin_memcpy(&u, &h, 4); return u;
}
__device__ __forceinline__ void split16(const float* v, uint4* outH, uint4* outL) {
    uint32_t hp[8], lp[8];
#pragma unroll
    for (int p = 0; p < 8; p++) {
        float a0 = v[2 * p], a1 = v[2 * p + 1];
        __nv_bfloat162 h = __floats2bfloat162_rn(a0, a1);
        float r0 = a0 - __bfloat162float(h.x);
        float r1 = a1 - __bfloat162float(h.y);
        __nv_bfloat162 l = __floats2bfloat162_rn(r0, r1);
        hp[p] = bf2_u32(h); lp[p] = bf2_u32(l);
    }
    outH[0] = make_uint4(hp[0], hp[4], hp[1], hp[5]);
    outH[1] = make_uint4(hp[2], hp[6], hp[3], hp[7]);
    outL[0] = make_uint4(lp[0], lp[4], lp[1], lp[5]);
    outL[1] = make_uint4(lp[2], lp[6], lp[3], lp[7]);
}

// ---------------- K0w: precompute bf16-split packed W tiles ------------------
__global__ void k0w_prep(const float* __restrict__ Wk, const float* __restrict__ Wq) {
    const int task = blockIdx.x * 256 + threadIdx.x;
    const int mat = task >> 10, rem = task & 1023;
    const int n = rem >> 3, kg = rem & 7;
    const float* W = mat ? Wq : Wk;
    float v[16];
#pragma unroll
    for (int j = 0; j < 16; j++) v[j] = W[(size_t)(kg * 16 + j) * C_DIM + n];
    uint4 oh[2], ol[2];
    split16(v, oh, ol);
    const int base = n * 17 + kg * 2;
    g_Wsplit[mat][0][base]     = oh[0];
    g_Wsplit[mat][0][base + 1] = oh[1];
    g_Wsplit[mat][1][base]     = ol[0];
    g_Wsplit[mat][1][base + 1] = ol[1];
}

// ---------------- K0: tiny prep ----------------------------------------------
#define SMEM_K0_TOTAL ((128 * 132 + 1024) * 4)
__global__ void k0_prep(const float* __restrict__ Wp2,
                        const float* __restrict__ Ww1,
                        const float* __restrict__ bp2) {
    extern __shared__ float sp[];
    float* WpS = sp;
    float* W1s = sp + 128 * 132;
    const int tid = threadIdx.x;
    for (int i = tid; i < 4096; i += 256) {
        int r = i >> 5, q = i & 31;
        *(float4*)&WpS[r * 132 + q * 4] = *(const float4*)&Wp2[r * C_DIM + q * 4];
    }
    if (tid < 256) *(float4*)&W1s[tid * 4] = *(const float4*)&Ww1[tid * 4];
    __syncthreads();

    if (tid < 128) {
        const int c = tid;
        float acc[G_DIM];
#pragma unroll
        for (int g = 0; g < G_DIM; g++) acc[g] = 0.f;
        const float* wr = &WpS[c * 132];
#pragma unroll 8
        for (int c2 = 0; c2 < C_DIM; c2++) {
            float a = wr[c2];
#pragma unroll
            for (int g = 0; g < G_DIM; g++) acc[g] = fmaf(a, W1s[c2 * G_DIM + g], acc[g]);
        }
#pragma unroll
        for (int g = 0; g < G_DIM; g++) g_WpwT[g * C_DIM + c] = acc[g];
    } else if (tid < 128 + G_DIM) {
        const int g = tid - 128;
        float s = 0.f;
        for (int c2 = 0; c2 < C_DIM; c2++) s = fmaf(bp2[c2], W1s[c2 * G_DIM + g], s);
        g_pwb[g] = s;
    }
}

// ---------------- K12: fused context+query pass (R14: smem B, occ 2) ---------
#define K1_ROWB 272
__device__ __forceinline__ uint32_t k1_off(int row, int k) {
    int p = k >> 1;
    return (uint32_t)row * K1_ROWB + (uint32_t)(k >> 4) * 32
         + (uint32_t)(p & 3) * 8 + (uint32_t)((p >> 2) & 1) * 4;
}

#define SM_AH   0
#define SM_AL   17408
#define SM_BH   34816
#define SM_BL   69632
#define SM_PAR  104448
#define SM_W1T  106496   // float[8][132]
#define SM_KS   0        // float[64][132]
#define SMEM_K12_TOTAL 110720

__launch_bounds__(256, 2)
__global__ void k12_proj(const float* __restrict__ cf, const float* __restrict__ qf,
                         const float* __restrict__ bk,
                         const float* __restrict__ gk, const float* __restrict__ betak,
                         const float* __restrict__ bq,
                         const float* __restrict__ gq, const float* __restrict__ betaq,
                         const float* __restrict__ Ww1, int NB) {
    extern __shared__ char smem[];
    const int tid = threadIdx.x;
    const int wid = tid >> 5;
    const int lane = tid & 31;
    const int grp = lane >> 2, tig = lane & 3;

    const bool ctx = (int)blockIdx.x < NB;
    const int bm0 = (ctx ? (int)blockIdx.x : (int)blockIdx.x - NB) * 64;
    const float* feat = ctx ? cf : qf;
    const float* bb   = ctx ? bk : bq;
    const float* gg   = ctx ? gk : gq;
    const float* be   = ctx ? betak : betaq;
    float* dst        = ctx ? g_kw : g_qw;
    const int mat     = ctx ? 0 : 1;

#pragma unroll
    for (int s2 = 0; s2 < 2; s2++) {
        int task = tid + s2 * 256;
        int row = task >> 3, kg = task & 7;
        const float4* src = (const float4*)&feat[(size_t)(bm0 + row) * C_DIM + kg * 16];
        float v[16];
        float4 x0 = src[0], x1 = src[1], x2 = src[2], x3 = src[3];
        v[0]=x0.x; v[1]=x0.y; v[2]=x0.z; v[3]=x0.w;
        v[4]=x1.x; v[5]=x1.y; v[6]=x1.z; v[7]=x1.w;
        v[8]=x2.x; v[9]=x2.y; v[10]=x2.z; v[11]=x2.w;
        v[12]=x3.x; v[13]=x3.y; v[14]=x3.z; v[15]=x3.w;
        uint4 oh[2], ol[2];
        split16(v, oh, ol);
        uint4* dH = (uint4*)(smem + SM_AH + row * K1_ROWB + kg * 32);
        uint4* dL = (uint4*)(smem + SM_AL + row * K1_ROWB + kg * 32);
        dH[0] = oh[0]; dH[1] = oh[1];
        dL[0] = ol[0]; dL[1] = ol[1];
    }
    {
        const uint4* WH = g_Wsplit[mat][0];
        const uint4* WL = g_Wsplit[mat][1];
        uint4* BH = (uint4*)(smem + SM_BH);
        uint4* BL = (uint4*)(smem + SM_BL);
        for (int i = tid; i < 2176; i += 256) { BH[i] = WH[i]; BL[i] = WL[i]; }
    }
    const float rs = rsqrtf(1.f + EPS_BN);
    if (tid < C_DIM) {
        float4 pp; pp.x = bb[tid]; pp.y = gg[tid] * rs; pp.z = be[tid]; pp.w = 0.f;
        *(float4*)(smem + SM_PAR + tid * 16) = pp;
    }
    {
        float* W1T = (float*)(smem + SM_W1T);
        for (int i = tid; i < 1024; i += 256) {
            int c = i >> 3, g = i & 7;
            W1T[g * 132 + c] = Ww1[i];
        }
    }
    __syncthreads();

    const int rbase = (wid & 3) * 16;
    const int cbase = (wid >> 2) * 64;
    float acc[8][4];
#pragma unroll
    for (int nt = 0; nt < 8; nt++)
#pragma unroll
        for (int q = 0; q < 4; q++) acc[nt][q] = 0.f;

    const uint32_t aoff_lo = k1_off(rbase + grp, 0) + tig * 8;
    const uint32_t aoff_hi = k1_off(rbase + grp + 8, 0) + tig * 8;

#pragma unroll
    for (int ks = 0; ks < 8; ks++) {
        const uint32_t kb = ks * 32;
        ull alo_h = *(const ull*)(smem + SM_AH + aoff_lo + kb);
        ull ahi_h = *(const ull*)(smem + SM_AH + aoff_hi + kb);
        ull alo_l = *(const ull*)(smem + SM_AL + aoff_lo + kb);
        ull ahi_l = *(const ull*)(smem + SM_AL + aoff_hi + kb);
        uint32_t a0h = (uint32_t)alo_h, a2h = (uint32_t)(alo_h >> 32);
        uint32_t a1h = (uint32_t)ahi_h, a3h = (uint32_t)(ahi_h >> 32);
        uint32_t a0l = (uint32_t)alo_l, a2l = (uint32_t)(alo_l >> 32);
        uint32_t a1l = (uint32_t)ahi_l, a3l = (uint32_t)(ahi_l >> 32);
#pragma unroll
        for (int nt = 0; nt < 8; nt++) {
            uint32_t boff = (uint32_t)(cbase + nt * 8 + grp) * K1_ROWB + kb + tig * 8;
            ull bh = *(const ull*)(smem + SM_BH + boff);
            ull bl = *(const ull*)(smem + SM_BL + boff);
            uint32_t b0h = (uint32_t)bh, b1h = (uint32_t)(bh >> 32);
            uint32_t b0l = (uint32_t)bl, b1l = (uint32_t)(bl >> 32);
            mma_bf16(acc[nt], a0h, a1h, a2h, a3h, b0h, b1h);
            mma_bf16(acc[nt], a0h, a1h, a2h, a3h, b0l, b1l);
            mma_bf16(acc[nt], a0l, a1l, a2l, a3l, b0h, b1h);
        }
    }
    __syncthreads();

    {
        float* ks_s = (float*)(smem + SM_KS);
        const float4* par = (const float4*)(smem + SM_PAR);
        const int r0 = rbase + grp, r1 = r0 + 8;
#pragma unroll
        for (int nt = 0; nt < 8; nt++) {
            int col = cbase + nt * 8 + tig * 2;
            float4 p0 = par[col], p1 = par[col + 1];
            float2 lo, hi;
            lo.x = fmaxf(fmaf(acc[nt][0] + p0.x, p0.y, p0.z), 0.f);
            lo.y = fmaxf(fmaf(acc[nt][1] + p1.x, p1.y, p1.z), 0.f);
            hi.x = fmaxf(fmaf(acc[nt][2] + p0.x, p0.y, p0.z), 0.f);
            hi.y = fmaxf(fmaf(acc[nt][3] + p1.x, p1.y, p1.z), 0.f);
            *(float2*)&ks_s[r0 * 132 + col] = lo;
            *(float2*)&ks_s[r1 * 132 + col] = hi;
        }
    }
    __syncthreads();

    {
        const float* ks_s = (const float*)(smem + SM_KS);
        const float* W1T  = (const float*)(smem + SM_W1T);
#pragma unroll
        for (int s2 = 0; s2 < 2; s2++) {
            int task = tid + s2 * 256;
            int row = task >> 3, g = task & 7;
            const float4* kr = (const float4*)&ks_s[row * 132];
            const float4* wr = (const float4*)&W1T[g * 132];
            ull A = 0, B = 0, C = 0, D = 0;
#pragma unroll
            for (int j = 0; j < 32; j += 2) {
                float4 k0 = kr[j],     w0 = wr[j];
                float4 k1 = kr[j + 1], w1 = wr[j + 1];
                ffma2(A, ((const ull*)&k0)[0], ((const ull*)&w0)[0]);
                ffma2(B, ((const ull*)&k0)[1], ((const ull*)&w0)[1]);
                ffma2(C, ((const ull*)&k1)[0], ((const ull*)&w1)[0]);
                ffma2(D, ((const ull*)&k1)[1], ((const ull*)&w1)[1]);
            }
            float a0, a1, b0, b1, c0, c1, d0, d1;
            unpack2(A, a0, a1); unpack2(B, b0, b1);
            unpack2(C, c0, c1); unpack2(D, d0, d1);
            dst[(size_t)(bm0 + row) * G_DIM + g] =
                ((a0 + a1) + (b0 + b1)) + ((c0 + c1) + (d0 + d1));
        }
    }
}

// ---------------- K3: attention weights + U/H accumulation (FFMA2, occ6) -----
struct S3 {
    float WpwT[G_DIM * 132];
    float ww2s[G_DIM * G_DIM];
    float hs[2][KNN * 132];
    float e_s[KNN * G_DIM];
    float psum[4 * G_DIM];
    float wpsum[4 * G_DIM];
    float pos[2][KNN * 4];
    float kwg[2][KNN * G_DIM];
    float qw[2][G_DIM];
    float msk[2][KNN];
    int   idx[2][KNN];
};

__device__ __forceinline__ void gatherK(S3* s, const int* __restrict__ knn,
                                        const float* __restrict__ qcoord,
                                        const float* __restrict__ ccoord,
                                        int m, int p, int k) {
    int id = knn[(size_t)m * KNN + k];
    float mk = id >= 0 ? 1.f : 0.f;
    int id0 = id >= 0 ? id : 0;
    s->idx[p][k] = id0;
    s->msk[p][k] = mk;
    float qx = qcoord[m * 3 + 0], qy = qcoord[m * 3 + 1], qz = qcoord[m * 3 + 2];
    s->pos[p][k * 4 + 0] = (ccoord[(size_t)id0 * 3 + 0] - qx) * mk;
    s->pos[p][k * 4 + 1] = (ccoord[(size_t)id0 * 3 + 1] - qy) * mk;
    s->pos[p][k * 4 + 2] = (ccoord[(size_t)id0 * 3 + 2] - qz) * mk;
    const float4* kwp = (const float4*)&g_kw[(size_t)id0 * G_DIM];
    float4 a = kwp[0], b = kwp[1];
    float* kd = &s->kwg[p][k * 8];
    kd[0] = a.x * mk; kd[1] = a.y * mk; kd[2] = a.z * mk; kd[3] = a.w * mk;
    kd[4] = b.x * mk; kd[5] = b.y * mk; kd[6] = b.z * mk; kd[7] = b.w * mk;
}

__device__ __forceinline__ void p4_packed(S3& s, int bp, int mp, int c, int t,
                                          const float* cfpre) {
    ull uu01 = 0, uu23 = 0, uu45 = 0, uu67 = 0;
    ull hh01 = 0, hh23 = 0, hh45 = 0, hh67 = 0;
#pragma unroll
    for (int k = 0; k < KNN; k++) {
        float hk = s.hs[bp][k * 132 + c];
        ull hkp = pack2(hk);
        ull cvp = pack2(cfpre[k]);
        float4 ea = *(const float4*)&s.e_s[k * 8];
        float4 eb = *(const float4*)&s.e_s[k * 8 + 4];
        ull e01 = ((const ull*)&ea)[0], e23 = ((const ull*)&ea)[1];
        ull e45 = ((const ull*)&eb)[0], e67 = ((const ull*)&eb)[1];
        ffma2(uu01, cvp, e01); ffma2(uu23, cvp, e23);
        ffma2(uu45, cvp, e45); ffma2(uu67, cvp, e67);
        ffma2(hh01, hkp, e01); ffma2(hh23, hkp, e23);
        ffma2(hh45, hkp, e45); ffma2(hh67, hkp, e67);
    }
    float uu[G_DIM], hh[G_DIM];
    unpack2(uu01, uu[0], uu[1]); unpack2(uu23, uu[2], uu[3]);
    unpack2(uu45, uu[4], uu[5]); unpack2(uu67, uu[6], uu[7]);
    unpack2(hh01, hh[0], hh[1]); unpack2(hh23, hh[2], hh[3]);
    unpack2(hh45, hh[4], hh[5]); unpack2(hh67, hh[6], hh[7]);
    __half2* baseh = &g_Hs2h[(size_t)mp * (G_DIM * 128)];
#pragma unroll
    for (int g2 = 0; g2 < G_DIM; g2++)
        baseh[g2 * 128 + c] = __floats2half2_rn(uu[g2], hh[g2]);
    if (t < G_DIM) {
        g_sums[(size_t)mp * G_DIM + t] =
            s.psum[t] + s.psum[8 + t] + s.psum[16 + t] + s.psum[24 + t];
        g_wsr[(size_t)mp * G_DIM + t] =
            s.wpsum[t] + s.wpsum[8 + t] + s.wpsum[16 + t] + s.wpsum[24 + t];
    }
}

__launch_bounds__(128, 6)
__global__ void k3_attn(const float* __restrict__ qcoord, const float* __restrict__ ccoord,
                        const int*   __restrict__ knn, const float* __restrict__ cf,
                        const float* __restrict__ Wp1, const float* __restrict__ bp1,
                        const float* __restrict__ gp1, const float* __restrict__ betap1,
                        const float* __restrict__ bw1, const float* __restrict__ gw1,
                        const float* __restrict__ betaw1,
                        const float* __restrict__ Ww2, const float* __restrict__ bw2) {
    __shared__ S3 s;
    const int t = threadIdx.x;
    const int c = t;
    const int kB = t >> 3, gB = t & 7;
    const int w4 = t >> 5;
    const int lane = t & 31;
    const int lbase = lane & ~7;

    for (int i = t; i < G_DIM * C_DIM; i += 128) {
        int r = i >> 7, cc2 = i & 127;
        s.WpwT[r * 132 + cc2] = g_WpwT[i];
    }
    if (t < G_DIM * G_DIM) s.ww2s[t] = Ww2[t];

    const float rs  = rsqrtf(1.f + EPS_BN);
    const float sp1 = gp1[c] * rs;
    const float wf0 = Wp1[c] * sp1, wf1 = Wp1[C_DIM + c] * sp1, wf2 = Wp1[2 * C_DIM + c] * sp1;
    const float hb  = fmaf(bp1[c], sp1, betap1[c]);
    const float sw1  = gw1[gB] * rs;
    const float wb1f = fmaf(bw1[gB], sw1, betaw1[gB]);
    const float pwbB = g_pwb[gB];
    const float bw2B = bw2[gB];

    const int mb = blockIdx.x * 8;
    float cfpre[KNN];

    if (t < KNN)   gatherK(&s, knn, qcoord, ccoord, mb, 0, t);
    if (t < G_DIM) s.qw[0][t] = g_qw[(size_t)mb * G_DIM + t];
    __syncthreads();

    for (int qi = 0; qi < 8; qi++) {
        const int b = qi & 1;
        const int m = mb + qi;

        {
#pragma unroll
            for (int k = 0; k < KNN; k++) {
                const float* pp = &s.pos[b][k * 4];
                s.hs[b][k * 132 + c] =
                    fmaxf(fmaf(wf0, pp[0], fmaf(wf1, pp[1], fmaf(wf2, pp[2], hb))), 0.f);
            }
            if (qi < 7) {
                if (t < KNN)   gatherK(&s, knn, qcoord, ccoord, m + 1, b ^ 1, t);
                if (t < G_DIM) s.qw[b ^ 1][t] = g_qw[(size_t)(m + 1) * G_DIM + t];
            }
            if (qi > 0) p4_packed(s, b ^ 1, m - 1, c, t, cfpre);
        }
        __syncthreads();

        {
            float init = s.kwg[b][t] - s.qw[b][gB] + pwbB;
            ull A = (ull)__float_as_uint(init);
            ull B = 0, C = 0, D = 0;
            const float4* hr = (const float4*)&s.hs[b][kB * 132];
            const float4* wr = (const float4*)&s.WpwT[gB * 132];
#pragma unroll
            for (int j = 0; j < 32; j += 2) {
                float4 h0 = hr[j],     w0 = wr[j];
                float4 h1 = hr[j + 1], w1 = wr[j + 1];
                ffma2(A, ((const ull*)&h0)[0], ((const ull*)&w0)[0]);
                ffma2(B, ((const ull*)&h0)[1], ((const ull*)&w0)[1]);
                ffma2(C, ((const ull*)&h1)[0], ((const ull*)&w1)[0]);
                ffma2(D, ((const ull*)&h1)[1], ((const ull*)&w1)[1]);
            }
            float a0, a1, b0, b1, c0, c1, d0, d1;
            unpack2(A, a0, a1); unpack2(B, b0, b1);
            unpack2(C, c0, c1); unpack2(D, d0, d1);
            float part = ((a0 + a1) + (b0 + b1)) + ((c0 + c1) + (d0 + d1));
            float ts = fmaxf(fmaf(part, sw1, wb1f), 0.f);

            float lg = bw2B;
#pragma unroll
            for (int g2 = 0; g2 < G_DIM; g2++)
                lg = fmaf(__shfl_sync(0xffffffffu, ts, lbase + g2), s.ww2s[g2 * G_DIM + gB], lg);

            float e  = __expf(lg);
            float mk = s.msk[b][kB];
            float em = e * mk;
            s.e_s[t] = em;
            float es = e;
            es += __shfl_xor_sync(0xffffffffu, es, 8);
            es += __shfl_xor_sync(0xffffffffu, es, 16);
            float esm = em;
            esm += __shfl_xor_sync(0xffffffffu, esm, 8);
            esm += __shfl_xor_sync(0xffffffffu, esm, 16);
            if (lane < 8) { s.psum[w4 * 8 + gB] = es; s.wpsum[w4 * 8 + gB] = esm; }

            const int* ix = s.idx[b];
#pragma unroll
            for (int k = 0; k < KNN; k++) cfpre[k] = cf[(size_t)ix[k] * C_DIM + c];
        }
        __syncthreads();
    }

    p4_packed(s, 1, mb + 7, c, t, cfpre);
}

// ---------------- K4: epilogue via fp16 HMMA (occ 5) --------------------------
#define K4_AS_OFF 0
#define K4_BS_OFF (64 * 132 * 4)
#define SMEM_K4_TOTAL (64 * 132 * 4 + 16 * 132 * 4)   // 42240 B
__launch_bounds__(256, 5)
__global__ void k4_out(const float* __restrict__ Wv, const float* __restrict__ Wp2,
                       const float* __restrict__ bv, const float* __restrict__ bp2,
                       float* __restrict__ out) {
    extern __shared__ char s4raw[];
    __half2* As = (__half2*)(s4raw + K4_AS_OFF);   // [64][132]
    __half2* Bs = (__half2*)(s4raw + K4_BS_OFF);   // [16][132]
    const int m0 = blockIdx.x * 64;
    const int g  = blockIdx.y;
    const int tid = threadIdx.x;

    for (int i = tid; i < 2048; i += 256) {
        int r = i >> 5, q = i & 31;
        *(uint4*)&As[r * 132 + q * 4] =
            *(const uint4*)&g_Hs2h[((size_t)(m0 + r) * G_DIM + g) * 128 + q * 4];
    }
    for (int i = tid; i < 2048; i += 256) {
        int c2 = i >> 4, cc = i & 15;
        float wv = Wv[(size_t)c2 * C_DIM + g * 16 + cc];
        float wp = Wp2[(size_t)c2 * C_DIM + g * 16 + cc];
        Bs[cc * 132 + c2] = __floats2half2_rn(wv, wp);
    }
    __syncthreads();

    const int wid = tid >> 5, lane = tid & 31;
    const int grp = lane >> 2, tig = lane & 3;
    const int mt = wid & 3, nt = wid >> 2;
    const __half2* Ar0 = &As[(mt * 16 + grp) * 132];
    const __half2* Ar1 = &As[(mt * 16 + grp + 8) * 132];
    const __half2* Bc  = &Bs[(nt * 8 + grp) * 132];

    float acc[4] = {0.f, 0.f, 0.f, 0.f};
#pragma unroll
    for (int ks = 0; ks < 16; ks++) {
        const int cb = ks * 8;
        uint32_t a0 = *(const uint32_t*)&Ar0[cb + tig];
        uint32_t a1 = *(const uint32_t*)&Ar1[cb + tig];
        uint32_t a2 = *(const uint32_t*)&Ar0[cb + tig + 4];
        uint32_t a3 = *(const uint32_t*)&Ar1[cb + tig + 4];
        uint32_t b0 = *(const uint32_t*)&Bc[cb + tig];
        uint32_t b1 = *(const uint32_t*)&Bc[cb + tig + 4];
        mma_f16(acc, a0, a1, a2, a3, b0, b1);
    }

    const int mA = m0 + mt * 16 + grp;
    const int mB = mA + 8;
    const float invA = 1.f / g_sums[(size_t)mA * G_DIM + g];
    const float wsA  = g_wsr[(size_t)mA * G_DIM + g];
    const float invB = 1.f / g_sums[(size_t)mB * G_DIM + g];
    const float wsB  = g_wsr[(size_t)mB * G_DIM + g];
    const int c0 = g * 16 + nt * 8 + 2 * tig;
    const float bb0 = bv[c0] + bp2[c0];
    const float bb1 = bv[c0 + 1] + bp2[c0 + 1];
    float2 oA, oB;
    oA.x = (acc[0] + bb0 * wsA) * invA;
    oA.y = (acc[1] + bb1 * wsA) * invA;
    oB.x = (acc[2] + bb0 * wsB) * invB;
    oB.y = (acc[3] + bb1 * wsB) * invB;
    *(float2*)&out[(size_t)mA * C_DIM + c0] = oA;
    *(float2*)&out[(size_t)mB * C_DIM + c0] = oB;
}

// ---------------- launch -----------------------------------------------------
extern "C" void kernel_launch(void* const* d_in, const int* in_sizes, int n_in,
                              void* d_out, int out_size) {
    const float* qf     = (const float*)d_in[0];
    const float* cf     = (const float*)d_in[1];
    const float* qc     = (const float*)d_in[2];
    const float* cc     = (const float*)d_in[3];
    const float* Wq     = (const float*)d_in[4];
    const float* bq     = (const float*)d_in[5];
    const float* gq     = (const float*)d_in[6];
    const float* betaq  = (const float*)d_in[7];
    const float* Wk     = (const float*)d_in[8];
    const float* bk     = (const float*)d_in[9];
    const float* gk     = (const float*)d_in[10];
    const float* betak  = (const float*)d_in[11];
    const float* Wv     = (const float*)d_in[12];
    const float* bv     = (const float*)d_in[13];
    const float* Wp1    = (const float*)d_in[14];
    const float* bp1    = (const float*)d_in[15];
    const float* gp1    = (const float*)d_in[16];
    const float* betap1 = (const float*)d_in[17];
    const float* Wp2    = (const float*)d_in[18];
    const float* bp2    = (const float*)d_in[19];
    const float* Ww1    = (const float*)d_in[20];
    const float* bw1    = (const float*)d_in[21];
    const float* gw1    = (const float*)d_in[22];
    const float* betaw1 = (const float*)d_in[23];
    const float* Ww2    = (const float*)d_in[24];
    const float* bw2    = (const float*)d_in[25];
    const int*   knn    = (const int*)d_in[26];
    float* out = (float*)d_out;

    const int M = in_sizes[0] / C_DIM;
    const int N = in_sizes[1] / C_DIM;
    const int NB = N / 64, MB = M / 64;

    k0w_prep<<<8, 256>>>(Wk, Wq);

    cudaFuncSetAttribute(k0_prep, cudaFuncAttributeMaxDynamicSharedMemorySize,
                         SMEM_K0_TOTAL);
    k0_prep<<<1, 256, SMEM_K0_TOTAL>>>(Wp2, Ww1, bp2);

    cudaFuncSetAttribute(k12_proj, cudaFuncAttributeMaxDynamicSharedMemorySize,
                         SMEM_K12_TOTAL);
    k12_proj<<<NB + MB, 256, SMEM_K12_TOTAL>>>(cf, qf, bk, gk, betak,
                                               bq, gq, betaq, Ww1, NB);

    k3_attn<<<M / 8, 128>>>(qc, cc, knn, cf, Wp1, bp1, gp1, betap1,
                            bw1, gw1, betaw1, Ww2, bw2);

    cudaFuncSetAttribute(k4_out, cudaFuncAttributeMaxDynamicSharedMemorySize,
                         SMEM_K4_TOTAL);
    dim3 g4(M / 64, G_DIM);
    k4_out<<<g4, 256, SMEM_K4_TOTAL>>>(Wv, Wp2, bv, bp2, out);
}